// round 1
// baseline (speedup 1.0000x reference)
#include <cuda_runtime.h>
#include <math.h>

#define EMB   512
#define BATCH 512

#define M_C   0.4f
#define H_C   0.333f
#define S_C   64.0f
#define EPS_C 1.0e-3f
#define PI_C  3.14159265358979323846f

#define BM 128
#define BN 128
#define BK 16
#define NT 256

__device__ float d_gang[BATCH];
__device__ float d_gadd[BATCH];
__device__ float d_ms[BATCH];
__device__ unsigned long long d_arg[BATCH];

// XOR swizzle on float index within a 128-float shared row:
// chunk (16B) index bits [0:1] ^= bits [3:4]  -> conflict-free LDS.128/STS.128
__device__ __forceinline__ int swz(int f) { return f ^ (((f >> 5) & 3) << 2); }

__device__ __forceinline__ void fma2(unsigned long long& d, unsigned long long a,
                                     unsigned long long b) {
    asm("fma.rn.f32x2 %0, %1, %2, %0;" : "+l"(d) : "l"(a), "l"(b));
}
__device__ __forceinline__ unsigned long long dup2(float f) {
    unsigned long long d;
    unsigned u = __float_as_uint(f);
    asm("mov.b64 %0, {%1, %1};" : "=l"(d) : "r"(u));
    return d;
}
__device__ __forceinline__ void unpk(unsigned long long v, float& lo, float& hi) {
    unsigned a, b;
    asm("mov.b64 {%0, %1}, %2;" : "=r"(a), "=r"(b) : "l"(v));
    lo = __uint_as_float(a);
    hi = __uint_as_float(b);
}

// ---------------------------------------------------------------------------
// Kernel 1: batch norm statistics -> margin scalars; reset argmax buffer
// ---------------------------------------------------------------------------
__global__ void stats_kernel(const float* __restrict__ norms) {
    __shared__ float red[BATCH];
    int t = threadIdx.x;
    float x = fminf(fmaxf(norms[t], 0.001f), 100.0f);
    red[t] = x;
    __syncthreads();
    for (int s = BATCH / 2; s > 0; s >>= 1) {
        if (t < s) red[t] += red[t + s];
        __syncthreads();
    }
    float mean = red[0] * (1.0f / BATCH);
    __syncthreads();
    float dv = x - mean;
    red[t] = dv * dv;
    __syncthreads();
    for (int s = BATCH / 2; s > 0; s >>= 1) {
        if (t < s) red[t] += red[t + s];
        __syncthreads();
    }
    float stdv = sqrtf(red[0] / (float)(BATCH - 1));   // ddof=1
    float ms = fminf(fmaxf((x - mean) / (stdv + EPS_C) * H_C, -1.0f), 1.0f);
    d_ms[t]   = ms;
    d_gang[t] = -M_C * ms;
    d_gadd[t] = M_C + M_C * ms;
    d_arg[t]  = 0ull;
}

// ---------------------------------------------------------------------------
// Kernel 2: fused SGEMM (f32x2) + column-norm + margin epilogue + argmax
//   A = emb [512, 512] row-major, B = kernel [512, N] row-major
// ---------------------------------------------------------------------------
__global__ void __launch_bounds__(NT, 2)
gemm_kernel(const float* __restrict__ A, const float* __restrict__ B,
            const int* __restrict__ label,
            float* __restrict__ out1, float* __restrict__ out2, int N)
{
    __shared__ float As[BK][BM];
    __shared__ float Bs[BK][BN];
    __shared__ float invn_s[BN];
    __shared__ int   lab_s[BM];
    __shared__ float gang_s[BM];
    __shared__ float gadd_s[BM];

    const int t  = threadIdx.x;
    const int m0 = blockIdx.x * BM;
    const int n0 = blockIdx.y * BN;

    if (t < BM) {
        lab_s[t]  = label[m0 + t];
        gang_s[t] = d_gang[m0 + t];
        gadd_s[t] = d_gadd[m0 + t];
    }

    const int a_r = t >> 2;            // 0..63
    const int a_c = (t & 3) << 2;      // 0,4,8,12
    const int b_r = t >> 5;            // 0..7
    const int b_c = (t & 31) << 2;     // 0..124
    const int tx  = t & 15;
    const int ty  = t >> 4;
    const int swb  = swz(b_c);
    const int swr0 = swz(tx * 8);
    const int swr1 = swz(tx * 8 + 4);

    const float* Ap0 = A + (size_t)(m0 + a_r) * EMB + a_c;
    const float* Ap1 = Ap0 + (size_t)64 * EMB;
    const float* Bp0 = B + (size_t)b_r * N + n0 + b_c;
    const float* Bp1 = Bp0 + (size_t)8 * N;
    const bool bvec = (n0 + b_c + 3 < N);

    float4 ra0, ra1, rb0, rb1;
    float ss0 = 0.f, ss1 = 0.f, ss2 = 0.f, ss3 = 0.f;

    // N is even but NOT a multiple of 4 -> B rows are only 8B-aligned: float2 loads.
    auto loadB = [&](int k) {
        const float* p0 = Bp0 + (size_t)k * N;
        const float* p1 = Bp1 + (size_t)k * N;
        if (bvec) {
            float2 x0 = *(const float2*)p0;
            float2 y0 = *(const float2*)(p0 + 2);
            float2 x1 = *(const float2*)p1;
            float2 y1 = *(const float2*)(p1 + 2);
            rb0 = make_float4(x0.x, x0.y, y0.x, y0.y);
            rb1 = make_float4(x1.x, x1.y, y1.x, y1.y);
        } else {
            rb0.x = (n0 + b_c + 0 < N) ? p0[0] : 0.f;
            rb0.y = (n0 + b_c + 1 < N) ? p0[1] : 0.f;
            rb0.z = (n0 + b_c + 2 < N) ? p0[2] : 0.f;
            rb0.w = 0.f;
            rb1.x = (n0 + b_c + 0 < N) ? p1[0] : 0.f;
            rb1.y = (n0 + b_c + 1 < N) ? p1[1] : 0.f;
            rb1.z = (n0 + b_c + 2 < N) ? p1[2] : 0.f;
            rb1.w = 0.f;
        }
    };

    ra0 = *(const float4*)Ap0;
    ra1 = *(const float4*)Ap1;
    loadB(0);

    unsigned long long acc[8][4];
#pragma unroll
    for (int i = 0; i < 8; i++)
#pragma unroll
        for (int j = 0; j < 4; j++) acc[i][j] = 0ull;

    for (int k0 = 0; k0 < EMB; k0 += BK) {
        // stage current registers into shared (A transposed, B swizzled)
        As[a_c + 0][a_r] = ra0.x;
        As[a_c + 1][a_r] = ra0.y;
        As[a_c + 2][a_r] = ra0.z;
        As[a_c + 3][a_r] = ra0.w;
        As[a_c + 0][a_r + 64] = ra1.x;
        As[a_c + 1][a_r + 64] = ra1.y;
        As[a_c + 2][a_r + 64] = ra1.z;
        As[a_c + 3][a_r + 64] = ra1.w;
        *(float4*)&Bs[b_r][swb]     = rb0;
        *(float4*)&Bs[b_r + 8][swb] = rb1;
        // fused column sum-of-squares (free: data already in regs)
        ss0 += rb0.x * rb0.x + rb1.x * rb1.x;
        ss1 += rb0.y * rb0.y + rb1.y * rb1.y;
        ss2 += rb0.z * rb0.z + rb1.z * rb1.z;
        ss3 += rb0.w * rb0.w + rb1.w * rb1.w;
        __syncthreads();

        int kn = k0 + BK;
        if (kn < EMB) {   // prefetch next stage before compute to hide LDG latency
            ra0 = *(const float4*)(Ap0 + kn);
            ra1 = *(const float4*)(Ap1 + kn);
            loadB(kn);
        }

#pragma unroll
        for (int kk = 0; kk < BK; kk++) {
            float4 af0 = *(const float4*)&As[kk][ty * 8];
            float4 af1 = *(const float4*)&As[kk][ty * 8 + 4];
            ulonglong2 bb0 = *(const ulonglong2*)&Bs[kk][swr0];
            ulonglong2 bb1 = *(const ulonglong2*)&Bs[kk][swr1];
            unsigned long long a2[8];
            a2[0] = dup2(af0.x); a2[1] = dup2(af0.y);
            a2[2] = dup2(af0.z); a2[3] = dup2(af0.w);
            a2[4] = dup2(af1.x); a2[5] = dup2(af1.y);
            a2[6] = dup2(af1.z); a2[7] = dup2(af1.w);
            unsigned long long b2[4] = {bb0.x, bb0.y, bb1.x, bb1.y};
#pragma unroll
            for (int i = 0; i < 8; i++)
#pragma unroll
                for (int j = 0; j < 4; j++)
                    fma2(acc[i][j], a2[i], b2[j]);   // packed f32x2 FMA
        }
        __syncthreads();
    }

    // reduce column sum-of-squares across the 8 loader row-groups (reuse As)
    {
        float* red = &As[0][0];
        int g = t >> 5;
        red[g * BN + b_c + 0] = ss0;
        red[g * BN + b_c + 1] = ss1;
        red[g * BN + b_c + 2] = ss2;
        red[g * BN + b_c + 3] = ss3;
    }
    __syncthreads();
    if (t < BN) {
        const float* red = &As[0][0];
        float s = 0.f;
#pragma unroll
        for (int g = 0; g < 8; g++) s += red[g * BN + t];
        invn_s[t] = rsqrtf(s);
    }
    __syncthreads();

    // Epilogue: cos -> clip -> (label margin) -> outputs + packed argmax
#pragma unroll
    for (int i = 0; i < 8; i++) {
        const int m  = ty * 8 + i;
        const int gm = m0 + m;
        const int lab  = lab_s[m];
        const float gang = gang_s[m];
        const float gadd = gadd_s[m];
        float o1[8], o2[8];
        unsigned long long best = 0ull;
#pragma unroll
        for (int j = 0; j < 4; j++) {
            float v0, v1;
            unpk(acc[i][j], v0, v1);
#pragma unroll
            for (int s = 0; s < 2; s++) {
                const int c  = tx * 8 + 2 * j + s;
                const int gc = n0 + c;
                float v = (s == 0) ? v0 : v1;
                float cosv = fminf(fmaxf(v * invn_s[c], -1.0f + EPS_C), 1.0f - EPS_C);
                float vm = cosv;
                float o1v = cosv * S_C;
                if (gc == lab) {  // clip(acos+g) is identity off-label
                    float th = fminf(fmaxf(acosf(cosv) + gang, EPS_C), PI_C - EPS_C);
                    vm  = cosf(th);
                    o1v = (vm - gadd) * S_C;
                }
                o1[2 * j + s] = o1v;
                o2[2 * j + s] = vm * S_C;
                if (gc < N) {
                    unsigned u = __float_as_uint(vm);
                    u = (u & 0x80000000u) ? ~u : (u | 0x80000000u); // order-preserving
                    unsigned long long key =
                        ((unsigned long long)u << 32) | (unsigned)(~(unsigned)gc);
                    best = best > key ? best : key;   // first-max tie-break
                }
            }
        }
        // reduce across the 16 tx lanes sharing this row
#pragma unroll
        for (int off = 8; off > 0; off >>= 1) {
            unsigned long long o = __shfl_xor_sync(0xFFFFFFFFu, best, off);
            best = best > o ? best : o;
        }
        if (tx == 0) atomicMax(&d_arg[gm], best);

        // streaming stores; row base only 8B-aligned (N % 4 == 2) -> float2
        size_t base = (size_t)gm * N + n0 + tx * 8;
        if (n0 + tx * 8 + 7 < N) {
            __stcs((float2*)(out1 + base),     make_float2(o1[0], o1[1]));
            __stcs((float2*)(out1 + base + 2), make_float2(o1[2], o1[3]));
            __stcs((float2*)(out1 + base + 4), make_float2(o1[4], o1[5]));
            __stcs((float2*)(out1 + base + 6), make_float2(o1[6], o1[7]));
            __stcs((float2*)(out2 + base),     make_float2(o2[0], o2[1]));
            __stcs((float2*)(out2 + base + 2), make_float2(o2[2], o2[3]));
            __stcs((float2*)(out2 + base + 4), make_float2(o2[4], o2[5]));
            __stcs((float2*)(out2 + base + 6), make_float2(o2[6], o2[7]));
        } else {
#pragma unroll
            for (int j = 0; j < 8; j++) {
                if (n0 + tx * 8 + j < N) {
                    out1[base + j] = o1[j];
                    out2[base + j] = o2[j];
                }
            }
        }
    }
}

// ---------------------------------------------------------------------------
// Kernel 3: apply second margin at the per-row argmax; write argmax/ms outputs
// ---------------------------------------------------------------------------
__global__ void fixup_kernel(float* __restrict__ out2,
                             float* __restrict__ oarg,
                             float* __restrict__ oms, int N) {
    int b = threadIdx.x;
    unsigned long long key = d_arg[b];
    unsigned hi = (unsigned)(key >> 32);
    unsigned lo = (unsigned)key;
    int col = (int)(~lo);
    float v = (hi & 0x80000000u) ? __uint_as_float(hi & 0x7FFFFFFFu)
                                 : __uint_as_float(~hi);
    // acos(cos_m) == theta_m on [eps, pi-eps]
    float th = fminf(fmaxf(acosf(v) + d_gang[b], EPS_C), PI_C - EPS_C);
    out2[(size_t)b * N + col] = (cosf(th) - d_gadd[b]) * S_C;
    oarg[b] = (float)col;
    oms[b]  = d_ms[b];
}

// ---------------------------------------------------------------------------
extern "C" void kernel_launch(void* const* d_in, const int* in_sizes, int n_in,
                              void* d_out, int out_size) {
    const float* emb   = (const float*)d_in[0];
    const float* norms = (const float*)d_in[1];
    const int*   label = (const int*)d_in[2];
    const float* kern  = (const float*)d_in[3];
    int N = in_sizes[3] / EMB;

    float* out1 = (float*)d_out;
    float* out2 = out1 + (size_t)BATCH * N;
    float* oarg = out2 + (size_t)BATCH * N;
    float* oms  = oarg + BATCH;

    stats_kernel<<<1, BATCH>>>(norms);
    dim3 grid(BATCH / BM, (N + BN - 1) / BN);   // x = M-tiles (fast) -> B tile L2 reuse
    gemm_kernel<<<grid, NT>>>(emb, kern, label, out1, out2, N);
    fixup_kernel<<<1, BATCH>>>(out2, oarg, oms, N);
}

// round 4
// speedup vs baseline: 1.5936x; 1.5936x over previous
#include <cuda_runtime.h>
#include <cuda_bf16.h>
#include <math.h>
#include <stdint.h>

#define EMB   512
#define BATCH 512
#define M_C   0.4f
#define H_C   0.333f
#define S_C   64.0f
#define EPS_C 1.0e-3f
#define PI_C  3.14159265358979323846f

#define BM  128
#define BN  128
#define BK  64
#define NT  256
#define KCH 8          // 512 / 64

// dynamic smem layout (bytes)
#define SM_AH(s) ((s) * 65536 + 0)
#define SM_AL(s) ((s) * 65536 + 16384)
#define SM_BH(s) ((s) * 65536 + 32768)
#define SM_BL(s) ((s) * 65536 + 49152)
#define SM_RED   131072
#define SM_INV   132096
#define SM_LAB   132608
#define SM_GANG  133120
#define SM_GADD  133632
#define SM_AMX   134144
#define SMEM_BYTES 138240

#define SWZ(x) ((x) ^ (((x) >> 3) & 0x70))   // 128B-row XOR swizzle

__device__ float d_gang[BATCH];
__device__ float d_gadd[BATCH];
__device__ float d_ms[BATCH];
__device__ unsigned long long d_arg[BATCH];
__device__ __align__(16) unsigned short d_Ah[BATCH * EMB];  // bf16 hi of emb
__device__ __align__(16) unsigned short d_Al[BATCH * EMB];  // bf16 lo of emb

// ---------------------------------------------------------------------------
__device__ __forceinline__ uint32_t smem_u32(const void* p) {
    uint32_t a;
    asm("{ .reg .u64 t; cvta.to.shared.u64 t, %1; cvt.u32.u64 %0, t; }"
        : "=r"(a) : "l"(p));
    return a;
}
__device__ __forceinline__ void cp16(uint32_t dst, const void* src) {
    asm volatile("cp.async.cg.shared.global [%0], [%1], 16;"
                 :: "r"(dst), "l"(src) : "memory");
}
#define CP_COMMIT() asm volatile("cp.async.commit_group;" ::: "memory")
#define CP_WAIT0()  asm volatile("cp.async.wait_group 0;" ::: "memory")

#define LDSM4(r, a) \
    asm volatile("ldmatrix.sync.aligned.m8n8.x4.shared.b16 {%0,%1,%2,%3}, [%4];" \
        : "=r"((r)[0]), "=r"((r)[1]), "=r"((r)[2]), "=r"((r)[3]) : "r"(a))
#define LDSM2(r, a) \
    asm volatile("ldmatrix.sync.aligned.m8n8.x2.shared.b16 {%0,%1}, [%2];" \
        : "=r"((r)[0]), "=r"((r)[1]) : "r"(a))

__device__ __forceinline__ void mma16816(float* c, const uint32_t* a,
                                         const uint32_t* b) {
    asm volatile(
        "mma.sync.aligned.m16n8k16.row.col.f32.bf16.bf16.f32 "
        "{%0,%1,%2,%3}, {%4,%5,%6,%7}, {%8,%9}, {%0,%1,%2,%3};"
        : "+f"(c[0]), "+f"(c[1]), "+f"(c[2]), "+f"(c[3])
        : "r"(a[0]), "r"(a[1]), "r"(a[2]), "r"(a[3]), "r"(b[0]), "r"(b[1]));
}

// two-level bf16 split of a pair of floats, packed as bf16x2
__device__ __forceinline__ void split2(float x0, float x1,
                                       uint32_t& hp, uint32_t& lp) {
    asm("cvt.rn.bf16x2.f32 %0, %1, %2;" : "=r"(hp) : "f"(x1), "f"(x0));
    float h0 = __uint_as_float(hp << 16);
    float h1 = __uint_as_float(hp & 0xffff0000u);
    float l0 = x0 - h0, l1 = x1 - h1;
    asm("cvt.rn.bf16x2.f32 %0, %1, %2;" : "=r"(lp) : "f"(l1), "f"(l0));
}

// ---------------------------------------------------------------------------
// Kernel 1: batch norm statistics -> margin scalars; reset argmax buffer
// ---------------------------------------------------------------------------
__global__ void stats_kernel(const float* __restrict__ norms) {
    __shared__ float red[BATCH];
    int t = threadIdx.x;
    float x = fminf(fmaxf(norms[t], 0.001f), 100.0f);
    red[t] = x;
    __syncthreads();
    for (int s = BATCH / 2; s > 0; s >>= 1) {
        if (t < s) red[t] += red[t + s];
        __syncthreads();
    }
    float mean = red[0] * (1.0f / BATCH);
    __syncthreads();
    float dv = x - mean;
    red[t] = dv * dv;
    __syncthreads();
    for (int s = BATCH / 2; s > 0; s >>= 1) {
        if (t < s) red[t] += red[t + s];
        __syncthreads();
    }
    float stdv = sqrtf(red[0] / (float)(BATCH - 1));  // ddof=1
    float ms = fminf(fmaxf((x - mean) / (stdv + EPS_C) * H_C, -1.0f), 1.0f);
    d_ms[t]   = ms;
    d_gang[t] = -M_C * ms;
    d_gadd[t] = M_C + M_C * ms;
    d_arg[t]  = 0ull;
}

// ---------------------------------------------------------------------------
// Kernel 1b: pre-split A (emb) into bf16 hi/lo
// ---------------------------------------------------------------------------
__global__ void asplit_kernel(const float* __restrict__ A) {
    int i = blockIdx.x * blockDim.x + threadIdx.x;  // 65536 float4s
    float4 v = ((const float4*)A)[i];
    uint32_t h0, l0, h1, l1;
    split2(v.x, v.y, h0, l0);
    split2(v.z, v.w, h1, l1);
    ((uint2*)d_Ah)[i] = make_uint2(h0, h1);
    ((uint2*)d_Al)[i] = make_uint2(l0, l1);
}

// ---------------------------------------------------------------------------
// Kernel 2: HMMA (mma.sync bf16 3-split) GEMM + column-norm + margin + argmax
// ---------------------------------------------------------------------------
__global__ void __launch_bounds__(NT, 1)
gemm_kernel(const float* __restrict__ B, const int* __restrict__ label,
            float* __restrict__ out1, float* __restrict__ out2, int N)
{
    extern __shared__ char smem[];
    const uint32_t sb = smem_u32(smem);
    const int tid  = threadIdx.x;
    const int wid  = tid >> 5, lane = tid & 31;
    const int wm   = wid & 1;        // m half (0: rows 0-63, 1: 64-127)
    const int wn   = wid >> 1;       // n quarter (0..3), base wn*32
    const int m0   = blockIdx.x * BM;
    const int n0   = blockIdx.y * BN;

    int*   lab_s  = (int*)(smem + SM_LAB);
    float* gang_s = (float*)(smem + SM_GANG);
    float* gadd_s = (float*)(smem + SM_GADD);
    float* red_s  = (float*)(smem + SM_RED);
    float* invn_s = (float*)(smem + SM_INV);
    unsigned long long* amx = (unsigned long long*)(smem + SM_AMX);

    if (tid < BM) {
        lab_s[tid]  = label[m0 + tid];
        gang_s[tid] = d_gang[m0 + tid];
        gadd_s[tid] = d_gadd[m0 + tid];
        amx[tid * 4 + 0] = 0ull; amx[tid * 4 + 1] = 0ull;
        amx[tid * 4 + 2] = 0ull; amx[tid * 4 + 3] = 0ull;
    }

    // B loading: this thread owns column (tid&127), k-half (tid>>7)
    const int ncl   = tid & 127;
    const int col   = n0 + ncl;
    const bool cv   = col < N;
    const int khalf = tid >> 7;      // 0 or 1 -> k rows [0,32) or [32,64)
    const float* bp = B + (size_t)(khalf * 32) * N + col;

    float rb[32];
    float sumsq = 0.0f;

    auto loadB = [&](int c) {
        const float* p = bp + (size_t)(c * BK) * N;
#pragma unroll
        for (int j = 0; j < 32; j++)
            rb[j] = cv ? __ldg(p + (size_t)j * N) : 0.0f;
    };
    auto putB = [&](int s) {
#pragma unroll
        for (int q = 0; q < 4; q++) {
            uint32_t hp[4], lp[4];
#pragma unroll
            for (int e = 0; e < 4; e++) {
                float x0 = rb[q * 8 + 2 * e], x1 = rb[q * 8 + 2 * e + 1];
                sumsq += x0 * x0 + x1 * x1;
                split2(x0, x1, hp[e], lp[e]);
            }
            uint32_t off = SWZ(ncl * 128 + (khalf * 4 + q) * 16);
            *(uint4*)(smem + SM_BH(s) + off) = make_uint4(hp[0], hp[1], hp[2], hp[3]);
            *(uint4*)(smem + SM_BL(s) + off) = make_uint4(lp[0], lp[1], lp[2], lp[3]);
        }
    };
    auto cpA = [&](int c, int s) {
#pragma unroll
        for (int q = 0; q < 4; q++) {
            int id = q * 256 + tid;
            int row = id >> 3, ch = id & 7;
            uint32_t off = SWZ(row * 128 + ch * 16);
            const size_t g = (size_t)(m0 + row) * EMB + c * BK + ch * 8;
            cp16(sb + SM_AH(s) + off, d_Ah + g);
            cp16(sb + SM_AL(s) + off, d_Al + g);
        }
        CP_COMMIT();
    };

    // prologue: stage 0
    loadB(0);
    cpA(0, 0);
    putB(0);
    CP_WAIT0();
    __syncthreads();

    float acc[4][4][4];
#pragma unroll
    for (int i = 0; i < 4; i++)
#pragma unroll
        for (int j = 0; j < 4; j++)
#pragma unroll
            for (int e = 0; e < 4; e++) acc[i][j][e] = 0.0f;

    // ldmatrix lane address components
    const int arow = ((lane >> 3) & 1) * 8 + (lane & 7);
    const int akb  = (lane >> 4) * 16;
    const int brow = (lane & 7);
    const int bkb  = ((lane >> 3) & 1) * 16;

    for (int c = 0; c < KCH; c++) {
        const int s = c & 1, s2 = (c + 1) & 1;
        if (c < KCH - 1) {
            cpA(c + 1, s2);
            loadB(c + 1);
        }
#pragma unroll
        for (int ks = 0; ks < 4; ks++) {
            uint32_t ah[4][4], al[4][4], bh[4][2], bl[4][2];
#pragma unroll
            for (int i = 0; i < 4; i++) {
                uint32_t off = SWZ((wm * 64 + i * 16 + arow) * 128 + ks * 32 + akb);
                LDSM4(ah[i], sb + SM_AH(s) + off);
                LDSM4(al[i], sb + SM_AL(s) + off);
            }
#pragma unroll
            for (int j = 0; j < 4; j++) {
                uint32_t off = SWZ((wn * 32 + j * 8 + brow) * 128 + ks * 32 + bkb);
                LDSM2(bh[j], sb + SM_BH(s) + off);
                LDSM2(bl[j], sb + SM_BL(s) + off);
            }
#pragma unroll
            for (int i = 0; i < 4; i++)
#pragma unroll
                for (int j = 0; j < 4; j++) {
                    mma16816(acc[i][j], ah[i], bh[j]);
                    mma16816(acc[i][j], ah[i], bl[j]);
                    mma16816(acc[i][j], al[i], bh[j]);
                }
        }
        if (c < KCH - 1) {
            putB(s2);
            CP_WAIT0();
        }
        __syncthreads();
    }

    // column inv-norms (2 k-half contributions per column)
    red_s[tid] = sumsq;
    __syncthreads();
    if (tid < BN)
        invn_s[tid] = rsqrtf(fmaxf(red_s[tid] + red_s[tid + BN], 1e-30f));
    __syncthreads();

    // ---- epilogue: margins + stores + argmax ----
#pragma unroll
    for (int i = 0; i < 4; i++) {
        const int r0 = wm * 64 + i * 16 + (lane >> 2);
#pragma unroll
        for (int rh = 0; rh < 2; rh++) {
            const int row = r0 + rh * 8;
            const int gm  = m0 + row;
            const int lab   = lab_s[row];
            const float gng = gang_s[row];
            const float gad = gadd_s[row];
            unsigned long long best = 0ull;
#pragma unroll
            for (int j = 0; j < 4; j++) {
                const int cl0 = wn * 32 + j * 8 + (lane & 3) * 2;
                const int gc0 = n0 + cl0;
                float o1v[2], o2v[2];
#pragma unroll
                for (int e = 0; e < 2; e++) {
                    float v = acc[i][j][rh * 2 + e] * invn_s[cl0 + e];
                    float cosv = fminf(fmaxf(v, -1.0f + EPS_C), 1.0f - EPS_C);
                    float vm = cosv, o1 = cosv * S_C;
                    if (gc0 + e == lab) {  // clip(acos+g) identity off-label
                        float th = fminf(fmaxf(acosf(cosv) + gng, EPS_C),
                                         PI_C - EPS_C);
                        vm = cosf(th);
                        o1 = (vm - gad) * S_C;
                    }
                    o1v[e] = o1;
                    o2v[e] = vm * S_C;
                    if (gc0 + e < N) {
                        unsigned u = __float_as_uint(vm);
                        u = (u & 0x80000000u) ? ~u : (u | 0x80000000u);
                        unsigned long long key =
                            ((unsigned long long)u << 32) |
                            (unsigned)(~(unsigned)(gc0 + e));
                        best = best > key ? best : key;
                    }
                }
                if (gc0 + 1 < N) {
                    const size_t gb = (size_t)gm * N + gc0;
                    __stcs((float2*)(out1 + gb), make_float2(o1v[0], o1v[1]));
                    __stcs((float2*)(out2 + gb), make_float2(o2v[0], o2v[1]));
                }
            }
            // reduce across the 4 lanes sharing this row
            {
                unsigned long long o = __shfl_xor_sync(0xFFFFFFFFu, best, 1);
                best = best > o ? best : o;
                o = __shfl_xor_sync(0xFFFFFFFFu, best, 2);
                best = best > o ? best : o;
            }
            if ((lane & 3) == 0) amx[row * 4 + wn] = best;
        }
    }
    __syncthreads();
    if (tid < BM) {
        unsigned long long b0 = amx[tid * 4 + 0], b1 = amx[tid * 4 + 1];
        unsigned long long b2 = amx[tid * 4 + 2], b3 = amx[tid * 4 + 3];
        unsigned long long b = b0 > b1 ? b0 : b1;
        b = b > b2 ? b : b2;
        b = b > b3 ? b : b3;
        atomicMax(&d_arg[m0 + tid], b);
    }
}

// ---------------------------------------------------------------------------
// Kernel 3: second margin at per-row argmax; write argmax/ms outputs
// ---------------------------------------------------------------------------
__global__ void fixup_kernel(float* __restrict__ out2,
                             float* __restrict__ oarg,
                             float* __restrict__ oms, int N) {
    int b = threadIdx.x;
    unsigned long long key = d_arg[b];
    unsigned hi = (unsigned)(key >> 32);
    unsigned lo = (unsigned)key;
    int col = (int)(~lo);
    float v = (hi & 0x80000000u) ? __uint_as_float(hi & 0x7FFFFFFFu)
                                 : __uint_as_float(~hi);
    float th = fminf(fmaxf(acosf(v) + d_gang[b], EPS_C), PI_C - EPS_C);
    out2[(size_t)b * N + col] = (cosf(th) - d_gadd[b]) * S_C;
    oarg[b] = (float)col;
    oms[b]  = d_ms[b];
}

// ---------------------------------------------------------------------------
extern "C" void kernel_launch(void* const* d_in, const int* in_sizes, int n_in,
                              void* d_out, int out_size) {
    const float* emb   = (const float*)d_in[0];
    const float* norms = (const float*)d_in[1];
    const int*   label = (const int*)d_in[2];
    const float* kern  = (const float*)d_in[3];
    int N = in_sizes[3] / EMB;

    float* out1 = (float*)d_out;
    float* out2 = out1 + (size_t)BATCH * N;
    float* oarg = out2 + (size_t)BATCH * N;
    float* oms  = oarg + BATCH;

    cudaFuncSetAttribute(gemm_kernel,
                         cudaFuncAttributeMaxDynamicSharedMemorySize, SMEM_BYTES);

    stats_kernel<<<1, BATCH>>>(norms);
    asplit_kernel<<<(BATCH * EMB / 4) / 256, 256>>>(emb);
    dim3 grid(BATCH / BM, (N + BN - 1) / BN);   // x = M fast -> B tile L2 reuse
    gemm_kernel<<<grid, NT, SMEM_BYTES>>>(kern, label, out1, out2, N);
    fixup_kernel<<<1, BATCH>>>(out2, oarg, oms, N);
}